// round 8
// baseline (speedup 1.0000x reference)
#include <cuda_runtime.h>
#include <cstdint>

#define NROWS 8191
#define C2    0.011271055006945017f    /* 2*gamma*log2(e), gamma=1/256 */
#define NGL2  0.0056355275034725085f   /* gamma*log2(e) */

// ---------------- device scratch (no allocation allowed) ----------------
__device__ float g_yt[8192 * 128];   // tf32-rounded yt (keys)
__device__ float g_vt[8192 * 128];   // tf32-rounded V rows: g_vt[j] = X[min(j+1,8191)]
__device__ float g_cq[8192];         // -gamma*log2e*||x_i||^2 (rounded x)
__device__ float g_ck[8192];         // -gamma*log2e*||yt_j||^2 ; row 8191 -> -1e30

// ---------------- helpers ----------------
__device__ __forceinline__ float tf32r(float x) {
    uint32_t u; asm("cvt.rna.tf32.f32 %0, %1;" : "=r"(u) : "f"(x));
    return __uint_as_float(u);
}
__device__ __forceinline__ float ex2f(float x) {
    float r; asm("ex2.approx.f32 %0, %1;" : "=f"(r) : "f"(x)); return r;
}
__device__ __forceinline__ uint32_t smaddr(const void* p) {
    uint32_t a;
    asm("{ .reg .u64 t; cvta.to.shared.u64 t, %1; cvt.u32.u64 %0, t; }" : "=r"(a) : "l"(p));
    return a;
}
#define CP16(dst, src) \
    asm volatile("cp.async.cg.shared.global [%0], [%1], 16;" \
                 :: "r"(dst), "l"((size_t)__cvta_generic_to_global(src)) : "memory")
#define CP_COMMIT() asm volatile("cp.async.commit_group;" ::: "memory")
#define CP_WAIT1()  asm volatile("cp.async.wait_group 1;" ::: "memory")
#define CP_WAIT0()  asm volatile("cp.async.wait_group 0;" ::: "memory")

__device__ __forceinline__ void mma8(float* c, uint32_t a0, uint32_t a1, uint32_t a2,
                                     uint32_t a3, uint32_t b0, uint32_t b1) {
    asm volatile("mma.sync.aligned.m16n8k8.row.col.f32.tf32.tf32.f32 "
                 "{%0,%1,%2,%3}, {%4,%5,%6,%7}, {%8,%9}, {%0,%1,%2,%3};"
                 : "+f"(c[0]), "+f"(c[1]), "+f"(c[2]), "+f"(c[3])
                 : "r"(a0), "r"(a1), "r"(a2), "r"(a3), "r"(b0), "r"(b1));
}

// ---------------- kernel 1: yt = y @ R^T + t (tf32-rounded at store) --------
__global__ __launch_bounds__(256) void yt_kernel(const float* __restrict__ y,
                                                 const float* __restrict__ R,
                                                 const float* __restrict__ t)
{
    extern __shared__ char smem[];
    float* yT = (float*)smem;                 // [k][row] stride 68
    float* RT = (float*)(smem + 34816);       // [k][c]   stride 132
    const int tid = threadIdx.x;
    const int r0  = blockIdx.x * 64;

    #pragma unroll
    for (int s = 0; s < 32; s++) {
        int e = tid + s * 256, row = e >> 7, k = e & 127, gr = r0 + row;
        yT[k * 68 + row] = (gr < NROWS) ? y[gr * 128 + k] : 0.0f;
    }
    #pragma unroll
    for (int s = 0; s < 64; s++) {
        int e = tid + s * 256, c = e >> 7, k = e & 127;
        RT[k * 132 + c] = R[e];
    }
    __syncthreads();

    const int tr = tid >> 4, tc = tid & 15;
    float acc[4][8];
    #pragma unroll
    for (int i = 0; i < 4; i++)
        #pragma unroll
        for (int j = 0; j < 8; j++) acc[i][j] = 0.0f;

    const float4* yT4 = (const float4*)yT;
    const float4* RT4 = (const float4*)RT;
    #pragma unroll 8
    for (int k = 0; k < 128; k++) {
        float4 a  = yT4[k * 17 + tr];
        float4 b0 = RT4[k * 33 + tc * 2];
        float4 b1 = RT4[k * 33 + tc * 2 + 1];
        float av[4] = {a.x, a.y, a.z, a.w};
        float bv[8] = {b0.x, b0.y, b0.z, b0.w, b1.x, b1.y, b1.z, b1.w};
        #pragma unroll
        for (int i = 0; i < 4; i++)
            #pragma unroll
            for (int j = 0; j < 8; j++) acc[i][j] += av[i] * bv[j];
    }
    float tv[8];
    #pragma unroll
    for (int j = 0; j < 8; j++) tv[j] = t[tc * 8 + j];
    float4* yt4 = (float4*)g_yt;
    #pragma unroll
    for (int i = 0; i < 4; i++) {
        int row = r0 + tr * 4 + i;
        float4 o0, o1;
        o0.x = tf32r(acc[i][0] + tv[0]); o0.y = tf32r(acc[i][1] + tv[1]);
        o0.z = tf32r(acc[i][2] + tv[2]); o0.w = tf32r(acc[i][3] + tv[3]);
        o1.x = tf32r(acc[i][4] + tv[4]); o1.y = tf32r(acc[i][5] + tv[5]);
        o1.z = tf32r(acc[i][6] + tv[6]); o1.w = tf32r(acc[i][7] + tv[7]);
        yt4[row * 32 + tc * 2]     = o0;
        yt4[row * 32 + tc * 2 + 1] = o1;
    }
}

// ---------------- kernel 2: scaled norms (from the values MMA will see) ----
__global__ __launch_bounds__(128) void norm_kernel(const float* __restrict__ X)
{
    const int row = blockIdx.x, which = blockIdx.y;
    float v = which ? g_yt[row * 128 + threadIdx.x]
                    : tf32r(X[row * 128 + threadIdx.x]);
    float s = v * v;
    #pragma unroll
    for (int o = 16; o; o >>= 1) s += __shfl_down_sync(0xFFFFFFFFu, s, o);
    __shared__ float red[4];
    if ((threadIdx.x & 31) == 0) red[threadIdx.x >> 5] = s;
    __syncthreads();
    if (threadIdx.x == 0) {
        float tot = -(red[0] + red[1] + red[2] + red[3]) * NGL2;
        if (which) g_ck[row] = (row < NROWS) ? tot : -1e30f;
        else       g_cq[row] = tot;
    }
}

// ---------------- kernel 3: V rows (shifted, clamped, tf32-rounded) --------
__global__ __launch_bounds__(256) void vt_kernel(const float* __restrict__ X)
{
    int f = blockIdx.x * 256 + threadIdx.x;     // float4 index, 262144 total
    int row = f >> 5, c4 = f & 31;
    int src = row + 1; if (src > 8191) src = 8191;   // clamp; weight is 0 anyway
    float4 v = ((const float4*)X)[src * 32 + c4];
    v.x = tf32r(v.x); v.y = tf32r(v.y); v.z = tf32r(v.z); v.w = tf32r(v.w);
    ((float4*)g_vt)[f] = v;
}

// ---------------- kernel 4: flash RBF attention, tf32 mma.sync --------------
// grid 128, 512 threads (16 warps). warp = (wm = w&3 -> m-strip, g = w>>2 -> 16-key group)
// smem (floats): Qs[64][132]@0  Ks[2][64][132]@8448  Vs[2][64][136]@25344
//                Ps[64][76]@42752  ck[2][64]@47616   total 47744 f = 190976 B
#define SQ 132
#define SV 136
#define SP 76
#define QSO 0
#define KSO(b) (8448 + (b) * 8448)
#define VSO(b) (25344 + (b) * 8704)
#define PSO 42752
#define CKO(b) (47616 + (b) * 64)
#define SMEM_BYTES (47744 * 4)

__global__ __launch_bounds__(512, 1) void attn_kernel(const float* __restrict__ X,
                                                      float* __restrict__ out)
{
    extern __shared__ float sm[];
    const int tid = threadIdx.x;
    const int w = tid >> 5, l = tid & 31;
    const int gid = l >> 2, tig = l & 3;
    const int wm = w & 3, g = w >> 2;         // m-strip / key-group
    const int m0 = wm * 16;
    const int kb0 = g * 16;                   // this group's key base in tile
    const int r0 = blockIdx.x * 64;

    // ---- stage Q (tf32-rounded) into Qs ----
    {
        const float4* X4 = (const float4*)X;
        #pragma unroll
        for (int i = 0; i < 4; i++) {
            int f = tid + i * 512, r = f >> 5, c4 = f & 31;
            float4 q = X4[(size_t)(r0 + r) * 32 + c4];
            float* d = &sm[QSO + r * SQ + c4 * 4];
            d[0] = tf32r(q.x); d[1] = tf32r(q.y); d[2] = tf32r(q.z); d[3] = tf32r(q.w);
        }
    }
    const float cq0 = g_cq[r0 + m0 + gid];
    const float cq1 = g_cq[r0 + m0 + gid + 8];

    // ---- prime tile 0 into buffer 0 ----
    #pragma unroll
    for (int i = 0; i < 4; i++) {
        int f = tid + i * 512, r = f >> 5, c4 = f & 31;
        CP16(smaddr(&sm[KSO(0) + r * SQ + c4 * 4]), g_yt + r * 128 + c4 * 4);
    }
    #pragma unroll
    for (int i = 0; i < 4; i++) {
        int f = tid + i * 512, r = f >> 5, c4 = f & 31;
        CP16(smaddr(&sm[VSO(0) + r * SV + c4 * 4]), g_vt + r * 128 + c4 * 4);
    }
    if (tid < 16) CP16(smaddr(&sm[CKO(0) + tid * 4]), g_ck + tid * 4);
    CP_COMMIT();

    float oa[16][4];
    #pragma unroll
    for (int i = 0; i < 16; i++)
        #pragma unroll
        for (int j = 0; j < 4; j++) oa[i][j] = 0.0f;
    float den0 = 0.0f, den1 = 0.0f;

    #pragma unroll 1
    for (int t = 0; t < 128; t++) {
        const int b = t & 1;

        if (t + 1 < 128) {                      // prefetch t+1 into buf b^1
            const int nb = b ^ 1;
            const int j0 = (t + 1) * 64;
            #pragma unroll
            for (int i = 0; i < 4; i++) {
                int f = tid + i * 512, r = f >> 5, c4 = f & 31;
                CP16(smaddr(&sm[KSO(nb) + r * SQ + c4 * 4]),
                     g_yt + (size_t)(j0 + r) * 128 + c4 * 4);
            }
            #pragma unroll
            for (int i = 0; i < 4; i++) {
                int f = tid + i * 512, r = f >> 5, c4 = f & 31;
                CP16(smaddr(&sm[VSO(nb) + r * SV + c4 * 4]),
                     g_vt + (size_t)(j0 + r) * 128 + c4 * 4);
            }
            if (tid < 16) CP16(smaddr(&sm[CKO(nb) + tid * 4]), g_ck + j0 + tid * 4);
            CP_COMMIT();
            CP_WAIT1();                          // tile t fully arrived
        } else {
            CP_WAIT0();
        }
        __syncthreads();

        // ---- GEMM1: S = Q @ K^T  (m16 x n16 x k128 per warp; keys kb0..kb0+15) ----
        float sa[2][4];
        #pragma unroll
        for (int i = 0; i < 2; i++)
            #pragma unroll
            for (int j = 0; j < 4; j++) sa[i][j] = 0.0f;

        const uint32_t* QsU = (const uint32_t*)&sm[QSO];
        const uint32_t* KsU = (const uint32_t*)&sm[KSO(b)];
        #pragma unroll
        for (int k0 = 0; k0 < 16; k0++) {
            uint32_t a0 = QsU[(m0 + gid) * SQ + k0 * 8 + tig];
            uint32_t a1 = QsU[(m0 + gid + 8) * SQ + k0 * 8 + tig];
            uint32_t a2 = QsU[(m0 + gid) * SQ + k0 * 8 + tig + 4];
            uint32_t a3 = QsU[(m0 + gid + 8) * SQ + k0 * 8 + tig + 4];
            #pragma unroll
            for (int n0 = 0; n0 < 2; n0++) {
                uint32_t b0 = KsU[(kb0 + n0 * 8 + gid) * SQ + k0 * 8 + tig];
                uint32_t b1 = KsU[(kb0 + n0 * 8 + gid) * SQ + k0 * 8 + tig + 4];
                mma8(sa[n0], a0, a1, a2, a3, b0, b1);
            }
        }

        // ---- P = 2^(C2*S + cq + ck) (tf32-rounded), den += P, store Ps ----
        const float* ckb = &sm[CKO(b)];
        #pragma unroll
        for (int n0 = 0; n0 < 2; n0++) {
            int cb = kb0 + n0 * 8 + 2 * tig;
            float ck0 = ckb[cb], ck1 = ckb[cb + 1];
            float p00 = tf32r(ex2f(fmaf(C2, sa[n0][0], cq0 + ck0)));
            float p01 = tf32r(ex2f(fmaf(C2, sa[n0][1], cq0 + ck1)));
            float p10 = tf32r(ex2f(fmaf(C2, sa[n0][2], cq1 + ck0)));
            float p11 = tf32r(ex2f(fmaf(C2, sa[n0][3], cq1 + ck1)));
            den0 += p00 + p01;
            den1 += p10 + p11;
            *(float2*)&sm[PSO + (m0 + gid) * SP + cb]     = make_float2(p00, p01);
            *(float2*)&sm[PSO + (m0 + gid + 8) * SP + cb] = make_float2(p10, p11);
        }
        __syncwarp();

        // ---- GEMM2: O += P @ V over this group's 16 keys (m16 x n128 x k16) ----
        const uint32_t* PsU = (const uint32_t*)&sm[PSO];
        const uint32_t* VsU = (const uint32_t*)&sm[VSO(b)];
        #pragma unroll
        for (int k0 = 0; k0 < 2; k0++) {
            uint32_t a0 = PsU[(m0 + gid) * SP + kb0 + k0 * 8 + tig];
            uint32_t a1 = PsU[(m0 + gid + 8) * SP + kb0 + k0 * 8 + tig];
            uint32_t a2 = PsU[(m0 + gid) * SP + kb0 + k0 * 8 + tig + 4];
            uint32_t a3 = PsU[(m0 + gid + 8) * SP + kb0 + k0 * 8 + tig + 4];
            #pragma unroll
            for (int n0 = 0; n0 < 16; n0++) {
                uint32_t b0 = VsU[(kb0 + k0 * 8 + tig) * SV + n0 * 8 + gid];
                uint32_t b1 = VsU[(kb0 + k0 * 8 + tig + 4) * SV + n0 * 8 + gid];
                mma8(oa[n0], a0, a1, a2, a3, b0, b1);
            }
        }
        __syncthreads();                         // release buf b for tile t+2
    }

    // ---- cross-group reduction ----
    den0 += __shfl_xor_sync(0xFFFFFFFFu, den0, 1);
    den0 += __shfl_xor_sync(0xFFFFFFFFu, den0, 2);
    den1 += __shfl_xor_sync(0xFFFFFFFFu, den1, 1);
    den1 += __shfl_xor_sync(0xFFFFFFFFu, den1, 2);

    const int rl0 = m0 + gid, rl1 = rl0 + 8;     // local rows 0..63
    if (g) {
        float* ob = &sm[(g == 1) ? KSO(0) : (g == 2) ? KSO(1) : VSO(0)];
        #pragma unroll
        for (int n0 = 0; n0 < 16; n0++) {
            int col = n0 * 8 + 2 * tig;
            *(float2*)&ob[rl0 * 132 + col] = make_float2(oa[n0][0], oa[n0][1]);
            *(float2*)&ob[rl1 * 132 + col] = make_float2(oa[n0][2], oa[n0][3]);
        }
        if (tig == 0) {
            sm[PSO + (g - 1) * 64 + rl0] = den0;
            sm[PSO + (g - 1) * 64 + rl1] = den1;
        }
    }
    __syncthreads();
    if (g == 0) {
        const float* b1 = &sm[KSO(0)];
        const float* b2 = &sm[KSO(1)];
        const float* b3 = &sm[VSO(0)];
        den0 += sm[PSO + rl0] + sm[PSO + 64 + rl0] + sm[PSO + 128 + rl0];
        den1 += sm[PSO + rl1] + sm[PSO + 64 + rl1] + sm[PSO + 128 + rl1];
        const float i0 = 1.0f / den0, i1 = 1.0f / den1;
        const int row0 = r0 + rl0, row1 = r0 + rl1;
        #pragma unroll
        for (int n0 = 0; n0 < 16; n0++) {
            int col = n0 * 8 + 2 * tig;
            float2 u1 = *(const float2*)&b1[rl0 * 132 + col];
            float2 u2 = *(const float2*)&b2[rl0 * 132 + col];
            float2 u3 = *(const float2*)&b3[rl0 * 132 + col];
            if (row0 < NROWS)
                *(float2*)&out[(size_t)row0 * 128 + col] =
                    make_float2((oa[n0][0] + u1.x + u2.x + u3.x) * i0,
                                (oa[n0][1] + u1.y + u2.y + u3.y) * i0);
            float2 v1 = *(const float2*)&b1[rl1 * 132 + col];
            float2 v2 = *(const float2*)&b2[rl1 * 132 + col];
            float2 v3 = *(const float2*)&b3[rl1 * 132 + col];
            if (row1 < NROWS)
                *(float2*)&out[(size_t)row1 * 128 + col] =
                    make_float2((oa[n0][2] + v1.x + v2.x + v3.x) * i1,
                                (oa[n0][3] + v1.y + v2.y + v3.y) * i1);
        }
    }
}

// ---------------- launch ----------------------------------------------------
extern "C" void kernel_launch(void* const* d_in, const int* in_sizes, int n_in,
                              void* d_out, int out_size)
{
    const float* X = (const float*)d_in[0];   // (8192,128)
    const float* y = (const float*)d_in[1];   // (8191,128)
    const float* R = (const float*)d_in[3];   // (128,128)
    const float* t = (const float*)d_in[4];   // (128,1)
    float* out = (float*)d_out;               // (8191,128)

    cudaFuncSetAttribute(yt_kernel,   cudaFuncAttributeMaxDynamicSharedMemorySize, 102400);
    cudaFuncSetAttribute(attn_kernel, cudaFuncAttributeMaxDynamicSharedMemorySize, SMEM_BYTES);

    yt_kernel<<<128, 256, 102400>>>(y, R, t);
    norm_kernel<<<dim3(8192, 2), 128>>>(X);
    vt_kernel<<<1024, 256>>>(X);
    attn_kernel<<<128, 512, SMEM_BYTES>>>(X, out);
}